// round 16
// baseline (speedup 1.0000x reference)
#include <cuda_runtime.h>
#include <cuda_fp16.h>
#include <math.h>
#include <stdint.h>

#define N_HEAD   16
#define HEAD     128
#define ROPE     32
#define C_       2048
#define B_       2
#define T_       2048
#define M_TOK    (B_*T_)        // 4096
#define QKV_OUT  3072
#define FFN      8192

// ---------------- scratch (device globals; no allocations allowed) -------------
__device__ __half g_ln1[(size_t)M_TOK * C_];
__device__ __half g_ln2[(size_t)M_TOK * C_];
__device__ float  g_qkv[(size_t)M_TOK * QKV_OUT];
__device__ __half g_y  [(size_t)M_TOK * C_];
__device__ float  g_h  [(size_t)M_TOK * C_];
__device__ float  g_mlp[(size_t)M_TOK * C_];
__device__ __half g_act[(size_t)M_TOK * FFN];
// transposed fp16 weights, [N][K]
__device__ __half g_wqkv_t[(size_t)QKV_OUT * C_];
__device__ __half g_wproj_t[(size_t)C_ * C_];
__device__ __half g_wfc1_t[(size_t)FFN * C_];
__device__ __half g_wfc2_t[(size_t)C_ * FFN];

// ---------------- helpers --------------------------------------------------------
__device__ __forceinline__ void mma_f16(float* c, const uint32_t* a, const uint32_t* b) {
    asm volatile(
        "mma.sync.aligned.m16n8k16.row.col.f32.f16.f16.f32 "
        "{%0,%1,%2,%3}, {%4,%5,%6,%7}, {%8,%9}, {%0,%1,%2,%3};"
        : "+f"(c[0]), "+f"(c[1]), "+f"(c[2]), "+f"(c[3])
        : "r"(a[0]), "r"(a[1]), "r"(a[2]), "r"(a[3]),
          "r"(b[0]), "r"(b[1]));
}

__device__ __forceinline__ void cp16(void* smem, const void* gmem) {
    uint32_t sa = (uint32_t)__cvta_generic_to_shared(smem);
    asm volatile("cp.async.cg.shared.global [%0], [%1], 16;" :: "r"(sa), "l"(gmem));
}
#define CP_COMMIT() asm volatile("cp.async.commit_group;" ::: "memory")
#define CP_WAIT(n)  asm volatile("cp.async.wait_group %0;" :: "n"(n) : "memory")

__device__ __forceinline__ uint32_t h2u(__half2 h) { return *(uint32_t*)&h; }

__device__ __forceinline__ void ldmatrix_x4(
    uint32_t& r0, uint32_t& r1, uint32_t& r2, uint32_t& r3, uint32_t smem_addr)
{
    asm volatile(
        "ldmatrix.sync.aligned.m8n8.x4.shared.b16 {%0,%1,%2,%3}, [%4];"
        : "=r"(r0), "=r"(r1), "=r"(r2), "=r"(r3) : "r"(smem_addr));
}

__device__ __forceinline__ void ldmatrix_x4_trans(
    uint32_t& r0, uint32_t& r1, uint32_t& r2, uint32_t& r3, uint32_t smem_addr)
{
    asm volatile(
        "ldmatrix.sync.aligned.m8n8.x4.trans.shared.b16 {%0,%1,%2,%3}, [%4];"
        : "=r"(r0), "=r"(r1), "=r"(r2), "=r"(r3) : "r"(smem_addr));
}

// ---------------- transpose device body -----------------------------------------
__device__ __forceinline__ void transpose_dev(
    const float* __restrict__ W, __half* __restrict__ Wt, int K, int N,
    int bx, int by, float (*t)[33], int tx, int ty)
{
    int k0 = bx * 64, n0 = by * 32;
#pragma unroll
    for (int i = 0; i < 64; i += 8)
        t[ty + i][tx] = W[(size_t)(k0 + ty + i) * N + n0 + tx];
    __syncthreads();
#pragma unroll
    for (int j = 0; j < 32; j += 8) {
        int n = n0 + ty + j;
        __half2 h = __floats2half2_rn(t[2 * tx][ty + j], t[2 * tx + 1][ty + j]);
        *(__half2*)&Wt[(size_t)n * K + k0 + 2 * tx] = h;
    }
}

// ---------------- LN device body (fp16 dual outputs, vectorized) -----------------
__device__ __forceinline__ void ln_dev(
    const float* __restrict__ x,
    const float* __restrict__ w1, const float* __restrict__ b1,
    const float* __restrict__ w2, const float* __restrict__ b2,
    __half* __restrict__ o1, __half* __restrict__ o2, int row)
{
    const float* xr = x + (size_t)row * C_;
    int tid = threadIdx.x;
    int c0 = tid * 8;

    float v[8];
    *(float4*)&v[0] = *(const float4*)(xr + c0);
    *(float4*)&v[4] = *(const float4*)(xr + c0 + 4);
    float s = 0.f, s2 = 0.f;
#pragma unroll
    for (int i = 0; i < 8; i++) { s += v[i]; s2 += v[i] * v[i]; }
#pragma unroll
    for (int o = 16; o; o >>= 1) {
        s  += __shfl_xor_sync(0xffffffffu, s,  o);
        s2 += __shfl_xor_sync(0xffffffffu, s2, o);
    }
    __shared__ float sh[16];
    __shared__ float mu_s, rstd_s;
    int w = tid >> 5;
    if ((tid & 31) == 0) { sh[w] = s; sh[w + 8] = s2; }
    __syncthreads();
    if (tid == 0) {
        float a = 0.f, b = 0.f;
#pragma unroll
        for (int i = 0; i < 8; i++) { a += sh[i]; b += sh[i + 8]; }
        float mu  = a * (1.0f / C_);
        float var = b * (1.0f / C_) - mu * mu;
        mu_s = mu;
        rstd_s = rsqrtf(var + 1e-5f);
    }
    __syncthreads();
    float mu = mu_s, rs = rstd_s;

    float w1v[8], b1v[8], w2v[8], b2v[8];
    *(float4*)&w1v[0] = *(const float4*)(w1 + c0);
    *(float4*)&w1v[4] = *(const float4*)(w1 + c0 + 4);
    *(float4*)&b1v[0] = *(const float4*)(b1 + c0);
    *(float4*)&b1v[4] = *(const float4*)(b1 + c0 + 4);
    *(float4*)&w2v[0] = *(const float4*)(w2 + c0);
    *(float4*)&w2v[4] = *(const float4*)(w2 + c0 + 4);
    *(float4*)&b2v[0] = *(const float4*)(b2 + c0);
    *(float4*)&b2v[4] = *(const float4*)(b2 + c0 + 4);

    uint32_t u1[4], u2[4];
#pragma unroll
    for (int j = 0; j < 4; j++) {
        float n0 = (v[2 * j] - mu) * rs, n1 = (v[2 * j + 1] - mu) * rs;
        u1[j] = h2u(__floats2half2_rn(n0 * w1v[2 * j] + b1v[2 * j],
                                      n1 * w1v[2 * j + 1] + b1v[2 * j + 1]));
        u2[j] = h2u(__floats2half2_rn(n0 * w2v[2 * j] + b2v[2 * j],
                                      n1 * w2v[2 * j + 1] + b2v[2 * j + 1]));
    }
    *(uint4*)(o1 + (size_t)row * C_ + c0) = make_uint4(u1[0], u1[1], u1[2], u1[3]);
    *(uint4*)(o2 + (size_t)row * C_ + c0) = make_uint4(u2[0], u2[1], u2[2], u2[3]);
}

// ---------------- fused prep: 4 transposes + dual LN in ONE launch ---------------
#define TB_QKV  3072   // (2048/64)*(3072/32)
#define TB_PROJ 2048
#define TB_FC1  8192
#define TB_FC2  8192
#define TB_ALL  (TB_QKV + TB_PROJ + TB_FC1 + TB_FC2)   // 21504
__global__ __launch_bounds__(256) void prep_kernel(
    const float* wqkv, __half* wqt, const float* wproj, __half* wpt,
    const float* wfc1, __half* w1t, const float* wfc2, __half* w2t,
    const float* x, const float* ln1w, const float* ln1b,
    const float* ln2w, const float* ln2b, __half* ln1, __half* ln2)
{
    __shared__ float t[64][33];
    int tx = threadIdx.x & 31, ty = threadIdx.x >> 5;
    int bi = blockIdx.x;
    if (bi < TB_QKV) {
        transpose_dev(wqkv, wqt, C_, QKV_OUT, bi % 32, bi / 32, t, tx, ty);
    } else if (bi < TB_QKV + TB_PROJ) {
        int li = bi - TB_QKV;
        transpose_dev(wproj, wpt, C_, C_, li % 32, li / 32, t, tx, ty);
    } else if (bi < TB_QKV + TB_PROJ + TB_FC1) {
        int li = bi - TB_QKV - TB_PROJ;
        transpose_dev(wfc1, w1t, C_, FFN, li % 32, li / 32, t, tx, ty);
    } else if (bi < TB_ALL) {
        int li = bi - TB_QKV - TB_PROJ - TB_FC1;
        transpose_dev(wfc2, w2t, FFN, C_, li % 128, li / 128, t, tx, ty);
    } else {
        ln_dev(x, ln1w, ln1b, ln2w, ln2b, ln1, ln2, bi - TB_ALL);
    }
}

// ---------------- RoPE in place on qkv (fp32) ------------------------------------
__global__ __launch_bounds__(320) void rope_kernel(
    float* __restrict__ qkv,
    const float* __restrict__ cosb, const float* __restrict__ sinb)
{
    int r = blockIdx.x;
    int t = r & (T_ - 1);
    int tid = threadIdx.x;
    int hh = tid >> 4;
    int i  = tid & 15;
    int col;
    if (hh < 16) col = ((hh >> 2) * 6 + (hh & 3)) * HEAD;
    else         col = ((hh - 16) * 6 + 4) * HEAD;
    float* p = qkv + (size_t)r * QKV_OUT + col;
    float c1 = cosb[t * ROPE + i],      s1 = sinb[t * ROPE + i];
    float c2 = cosb[t * ROPE + i + 16], s2 = sinb[t * ROPE + i + 16];
    float x1 = p[i], x2 = p[i + 16];
    p[i]      = x1 * c1 - x2 * s1;
    p[i + 16] = x2 * c2 + x1 * s2;
}

// ---------------- fp16 GEMM device body: 128x128x32, 8 warps, ldmatrix ----------
#define APADH 40
#define ASZH  (128 * APADH)
#define BSZH  (128 * APADH)
#define STGH  (ASZH + BSZH)
#define HSM_BYTES (3 * STGH * 2)       // 61440

template <int EPI>
__device__ __forceinline__ void hgemm_dev(
    const __half* __restrict__ A, const __half* __restrict__ Bt,
    const float* __restrict__ bias, void* __restrict__ Co,
    int N, int K, int bx, int by, __half* hsm)
{
    int tid = threadIdx.x;
    int lane = tid & 31, wid = tid >> 5;
    int wm = (wid >> 2) * 64;
    int wn = (wid & 3) * 32;
    int g  = lane >> 2;
    int tg = lane & 3;
    int bm = by * 128, bn = bx * 128;

    const __half* Agb = A  + (size_t)bm * K;
    const __half* Bgb = Bt + (size_t)bn * K;

    int lm_r = lane & 15;
    int lm_c = (lane >> 4) * 8;

    float acc[4][4][4];
#pragma unroll
    for (int mi = 0; mi < 4; mi++)
#pragma unroll
        for (int ni = 0; ni < 4; ni++)
#pragma unroll
            for (int r = 0; r < 4; r++) acc[mi][ni][r] = 0.f;

    int nIter = K >> 5;

    auto produce = [&](int it) {
        int s = it % 3;
        int k0 = it << 5;
        __half* As = hsm + s * STGH;
        __half* Bs = As + ASZH;
#pragma unroll
        for (int i = 0; i < 2; i++) {
            int idx = tid + 256 * i;
            int r = idx >> 2, c = (idx & 3) * 8;
            cp16(As + r * APADH + c, Agb + (size_t)r * K + k0 + c);
        }
#pragma unroll
        for (int i = 0; i < 2; i++) {
            int idx = tid + 256 * i;
            int r = idx >> 2, c = (idx & 3) * 8;
            cp16(Bs + r * APADH + c, Bgb + (size_t)r * K + k0 + c);
        }
        CP_COMMIT();
    };

    produce(0);
    produce(1);

    for (int it = 0; it < nIter; it++) {
        int s = it % 3;
        if (it + 1 < nIter) { CP_WAIT(1); } else { CP_WAIT(0); }
        __syncthreads();
        if (it + 2 < nIter) produce(it + 2);

        const __half* As = hsm + s * STGH;
        const __half* Bs = As + ASZH;
        uint32_t a_u32 = (uint32_t)__cvta_generic_to_shared(As);
        uint32_t b_u32 = (uint32_t)__cvta_generic_to_shared(Bs);

#pragma unroll
        for (int ks = 0; ks < 2; ks++) {
            int kh = ks * 16;
            uint32_t af[4][4], bf[2][4];
#pragma unroll
            for (int mi = 0; mi < 4; mi++) {
                uint32_t addr = a_u32 +
                    (uint32_t)(((wm + mi * 16 + lm_r) * APADH + kh + lm_c) * 2);
                ldmatrix_x4(af[mi][0], af[mi][1], af[mi][2], af[mi][3], addr);
            }
#pragma unroll
            for (int n2 = 0; n2 < 2; n2++) {
                uint32_t addr = b_u32 +
                    (uint32_t)(((wn + n2 * 16 + lm_r) * APADH + kh + lm_c) * 2);
                ldmatrix_x4(bf[n2][0], bf[n2][1], bf[n2][2], bf[n2][3], addr);
            }
#pragma unroll
            for (int mi = 0; mi < 4; mi++)
#pragma unroll
                for (int ni = 0; ni < 4; ni++) {
                    int n2 = ni >> 1, lo = ni & 1;
                    uint32_t b[2] = { bf[n2][lo], bf[n2][lo + 2] };
                    mma_f16(acc[mi][ni], af[mi], b);
                }
        }
    }

#pragma unroll
    for (int mi = 0; mi < 4; mi++) {
#pragma unroll
        for (int rr = 0; rr < 2; rr++) {
            int m = bm + wm + mi * 16 + g + rr * 8;
            size_t rowoff = (size_t)m * N;
#pragma unroll
            for (int ni = 0; ni < 4; ni++) {
                int n = bn + wn + ni * 8 + tg * 2;
                float v0 = acc[mi][ni][rr * 2 + 0] + bias[n];
                float v1 = acc[mi][ni][rr * 2 + 1] + bias[n + 1];
                if (EPI == 1) {
                    v0 = 0.5f * v0 * (1.f + erff(v0 * 0.70710678118654752f));
                    v1 = 0.5f * v1 * (1.f + erff(v1 * 0.70710678118654752f));
                    *(__half2*)((__half*)Co + rowoff + n) = __floats2half2_rn(v0, v1);
                } else {
                    *(float2*)((float*)Co + rowoff + n) = make_float2(v0, v1);
                }
            }
        }
    }
}

// standalone GEMM wrapper (used for QKV)
template <int EPI>
__global__ __launch_bounds__(256, 2) void hgemm_kernel(
    const __half* __restrict__ A, const __half* __restrict__ Bt,
    const float* __restrict__ bias, void* __restrict__ Co, int N, int K)
{
    extern __shared__ __half hsm[];
    hgemm_dev<EPI>(A, Bt, bias, Co, N, K, blockIdx.x, blockIdx.y, hsm);
}

// ---------------- attention device body (one 64-row q-tile, 128 threads) --------
#define QK_PAD 136
#define P_PAD  72
#define KV_HALVES (64 * QK_PAD)
#define ATT_HALF_BYTES ((64 * QK_PAD + KV_HALVES + 64 * P_PAD) * 2)  // 44032
#define F1_SMEM (2 * ATT_HALF_BYTES)                                 // 88064

__device__ __forceinline__ void attn_dev(
    const float* __restrict__ qkv, __half* __restrict__ y,
    int qt, int myN, int maxN, int hh, int bb, __half* sm, int tid128)
{
    __half* Qs  = sm;
    __half* KVs = sm + 64 * QK_PAD;
    __half* Ps  = KVs + KV_HALVES;

    int gq = hh >> 2;
    int qcol = (gq * 6 + (hh & 3)) * HEAD;
    int kcol = (gq * 6 + 4) * HEAD;
    int vcol = (gq * 6 + 5) * HEAD;

    int lane = tid128 & 31, w = tid128 >> 5;
    int g = lane >> 2, tg = lane & 3;
    int qbase = qt * 64;
    const size_t RS = QKV_OUT;
    const float scale = 0.08838834764831845f;

    int lm_row = ((lane >> 3) & 1) * 8 + (lane & 7);
    int lm_dim = (lane >> 4) * 8;
    uint32_t v_u32 = (uint32_t)__cvta_generic_to_shared(KVs);

    for (int idx = tid128; idx < 64 * 32; idx += 128) {
        int rr = idx >> 5, dd = (idx & 31) * 4;
        float4 q = *(const float4*)(qkv + (size_t)(bb * T_ + qbase + rr) * RS + qcol + dd);
        uint2 u = make_uint2(h2u(__floats2half2_rn(q.x * scale, q.y * scale)),
                             h2u(__floats2half2_rn(q.z * scale, q.w * scale)));
        *(uint2*)&Qs[rr * QK_PAD + dd] = u;
    }

    float o[16][4];
#pragma unroll
    for (int nt = 0; nt < 16; nt++)
#pragma unroll
        for (int c = 0; c < 4; c++) o[nt][c] = 0.f;
    float rmax0 = -1e30f, rmax1 = -1e30f;
    float rsum0 = 0.f,    rsum1 = 0.f;

    int row0 = qbase + w * 16 + g;
    int row1 = row0 + 8;

    for (int kt = 0; kt < maxN; kt++) {
        int nb = kt * 64;
        bool act = (kt < myN);
        __syncthreads();
        if (act) {
            for (int idx = tid128; idx < 64 * 32; idx += 128) {
                int rr = idx >> 5, dd = (idx & 31) * 4;
                float4 k = *(const float4*)(qkv + (size_t)(bb * T_ + nb + rr) * RS + kcol + dd);
                uint2 u = make_uint2(h2u(__floats2half2_rn(k.x, k.y)),
                                     h2u(__floats2half2_rn(k.z, k.w)));
                *(uint2*)&KVs[rr * QK_PAD + dd] = u;
            }
        }
        __syncthreads();

        if (act) {
            float s[8][4];
#pragma unroll
            for (int nt = 0; nt < 8; nt++)
#pragma unroll
                for (int c = 0; c < 4; c++) s[nt][c] = 0.f;

#pragma unroll
            for (int ks = 0; ks < 8; ks++) {
                int kh = ks * 16;
                uint32_t a[4];
                a[0] = *(const uint32_t*)&Qs[(w * 16 + g) * QK_PAD + kh + 2 * tg];
                a[1] = *(const uint32_t*)&Qs[(w * 16 + g + 8) * QK_PAD + kh + 2 * tg];
                a[2] = *(const uint32_t*)&Qs[(w * 16 + g) * QK_PAD + kh + 2 * tg + 8];
                a[3] = *(const uint32_t*)&Qs[(w * 16 + g + 8) * QK_PAD + kh + 2 * tg + 8];
#pragma unroll
                for (int nt = 0; nt < 8; nt++) {
                    uint32_t bf[2];
                    bf[0] = *(const uint32_t*)&KVs[(nt * 8 + g) * QK_PAD + kh + 2 * tg];
                    bf[1] = *(const uint32_t*)&KVs[(nt * 8 + g) * QK_PAD + kh + 2 * tg + 8];
                    mma_f16(s[nt], a, bf);
                }
            }

            bool diag = (kt == qt);
            float ml0 = -1e30f, ml1 = -1e30f;
#pragma unroll
            for (int nt = 0; nt < 8; nt++) {
                int colb = nb + nt * 8 + tg * 2;
                float v0 = s[nt][0], v1 = s[nt][1];
                float v2 = s[nt][2], v3 = s[nt][3];
                if (diag) {
                    if (colb     > row0) v0 = -1e30f;
                    if (colb + 1 > row0) v1 = -1e30f;
                    if (colb     > row1) v2 = -1e30f;
                    if (colb + 1 > row1) v3 = -1e30f;
                }
                s[nt][0] = v0; s[nt][1] = v1; s[nt][2] = v2; s[nt][3] = v3;
                ml0 = fmaxf(ml0, fmaxf(v0, v1));
                ml1 = fmaxf(ml1, fmaxf(v2, v3));
            }
            ml0 = fmaxf(ml0, __shfl_xor_sync(0xffffffffu, ml0, 1));
            ml0 = fmaxf(ml0, __shfl_xor_sync(0xffffffffu, ml0, 2));
            ml1 = fmaxf(ml1, __shfl_xor_sync(0xffffffffu, ml1, 1));
            ml1 = fmaxf(ml1, __shfl_xor_sync(0xffffffffu, ml1, 2));

            float nm0 = fmaxf(rmax0, ml0), nm1 = fmaxf(rmax1, ml1);
            float f0 = __expf(rmax0 - nm0), f1 = __expf(rmax1 - nm1);
            rmax0 = nm0; rmax1 = nm1;

            float ps0 = 0.f, ps1 = 0.f;
#pragma unroll
            for (int nt = 0; nt < 8; nt++) {
                float p0 = __expf(s[nt][0] - nm0);
                float p1 = __expf(s[nt][1] - nm0);
                float p2 = __expf(s[nt][2] - nm1);
                float p3 = __expf(s[nt][3] - nm1);
                ps0 += p0 + p1;
                ps1 += p2 + p3;
                *(uint32_t*)&Ps[(w * 16 + g) * P_PAD + nt * 8 + 2 * tg] =
                    h2u(__floats2half2_rn(p0, p1));
                *(uint32_t*)&Ps[(w * 16 + g + 8) * P_PAD + nt * 8 + 2 * tg] =
                    h2u(__floats2half2_rn(p2, p3));
            }
            ps0 += __shfl_xor_sync(0xffffffffu, ps0, 1);
            ps0 += __shfl_xor_sync(0xffffffffu, ps0, 2);
            ps1 += __shfl_xor_sync(0xffffffffu, ps1, 1);
            ps1 += __shfl_xor_sync(0xffffffffu, ps1, 2);
            rsum0 = rsum0 * f0 + ps0;
            rsum1 = rsum1 * f1 + ps1;

#pragma unroll
            for (int nt = 0; nt < 16; nt++) {
                o[nt][0] *= f0; o[nt][1] *= f0;
                o[nt][2] *= f1; o[nt][3] *= f1;
            }
        }
        __syncthreads();

        if (act) {
            for (int idx = tid128; idx < 64 * 32; idx += 128) {
                int rr = idx >> 5, dd = (idx & 31) * 4;
                float4 v = *(const float4*)(qkv + (size_t)(bb * T_ + nb + rr) * RS + vcol + dd);
                uint2 u = make_uint2(h2u(__floats2half2_rn(v.x, v.y)),
                                     h2u(__floats2half2_rn(v.z, v.w)));
                *(uint2*)&KVs[rr * QK_PAD + dd] = u;
            }
        }
        __syncthreads();

        if (act) {
#pragma unroll
            for (int ks = 0; ks < 4; ks++) {
                int kh = ks * 16;
                uint32_t a[4];
                a[0] = *(const uint32_t*)&Ps[(w * 16 + g) * P_PAD + kh + 2 * tg];
                a[1] = *(const uint32_t*)&Ps[(w * 16 + g + 8) * P_PAD + kh + 2 * tg];
                a[2] = *(const uint32_t*)&Ps[(w * 16 + g) * P_PAD + kh + 2 * tg + 8];
                a[3] = *(const uint32_t*)&Ps[(w * 16 + g + 8) * P_PAD + kh + 2 * tg + 8];
#pragma unroll
                for (int ntp = 0; ntp < 8; ntp++) {
                    uint32_t addr = v_u32 +
                        (uint32_t)(((kh + lm_row) * QK_PAD + ntp * 16 + lm_dim) * 2);
                    uint32_t r0, r1, r2, r3;
                    ldmatrix_x4_trans(r0, r1, r2, r3, addr);
                    uint32_t b0[2] = {r0, r1};
                    uint32_t b1[2] = {r2, r3};
                    mma_f16(o[2 * ntp],     a, b0);
                    mma_f16(o[2 * ntp + 1], a, b1);
                }
            }
        }
    }

    float inv0 = 1.f / rsum0, inv1 = 1.f / rsum1;
    size_t m0 = (size_t)(bb * T_ + row0);
    size_t m1 = m0 + 8;
#pragma unroll
    for (int nt = 0; nt < 16; nt++) {
        int col = hh * HEAD + nt * 8 + tg * 2;
        *(__half2*)(y + m0 * C_ + col) = __floats2half2_rn(o[nt][0] * inv0, o[nt][1] * inv0);
        *(__half2*)(y + m1 * C_ + col) = __floats2half2_rn(o[nt][2] * inv1, o[nt][3] * inv1);
    }
}

// ---------------- fused1: attention interleaved with fc1 GEMM -------------------
// 2560 blocks. attn when bi%5==4 (512 blocks); fc1 otherwise (2048 blocks).
// Interleaving puts attn (latency-bound) and fc1 (tensor-bound) blocks in the
// same wave so they co-reside per SM.
__global__ __launch_bounds__(256, 2) void fused1_kernel(
    const float* __restrict__ qkv, __half* __restrict__ y,
    const __half* __restrict__ ln2, const __half* __restrict__ w1t,
    const float* __restrict__ bfc1, __half* __restrict__ act)
{
    extern __shared__ __half fsm[];
    int bi = blockIdx.x;
    if ((bi % 5) == 4) {
        int ai = bi / 5;                    // 0..511
        int p  = ai & 15;
        int hh = (ai >> 4) & 15;
        int bb = ai >> 8;
        int half = threadIdx.x >> 7;
        int tid128 = threadIdx.x & 127;
        int qt  = half ? (31 - p) : p;
        int myN = qt + 1;
        int maxN = 32 - p;
        __half* sm = fsm + half * (ATT_HALF_BYTES / 2);
        attn_dev(qkv, y, qt, myN, maxN, hh, bb, sm, tid128);
    } else {
        int li = bi - bi / 5;               // 0..2047
        hgemm_dev<1>(ln2, w1t, bfc1, act, FFN, C_, li & 63, li >> 6, fsm);
    }
}

// ---------------- fused2: proj (512 blocks) + fc2 (512 blocks), interleaved -----
__global__ __launch_bounds__(256, 2) void fused2_kernel(
    const __half* __restrict__ y,  const __half* __restrict__ wpt,
    const float* __restrict__ bproj, float* __restrict__ h,
    const __half* __restrict__ act, const __half* __restrict__ w2t,
    const float* __restrict__ bfc2, float* __restrict__ mlp)
{
    extern __shared__ __half fsm[];
    int bi = blockIdx.x;
    if (bi & 1) {
        int li = bi >> 1;
        hgemm_dev<0>(y, wpt, bproj, h, C_, C_, li & 15, li >> 4, fsm);
    } else {
        int li = bi >> 1;
        hgemm_dev<0>(act, w2t, bfc2, mlp, C_, FFN, li & 15, li >> 4, fsm);
    }
}

// ---------------- final residual add: out = mlp + h + x -------------------------
__global__ __launch_bounds__(256) void add_kernel(
    const float* __restrict__ mlp, const float* __restrict__ h,
    const float* __restrict__ x, float* __restrict__ out)
{
    size_t i = ((size_t)blockIdx.x * 256 + threadIdx.x) * 4;
    float4 a = *(const float4*)(mlp + i);
    float4 b = *(const float4*)(h + i);
    float4 c = *(const float4*)(x + i);
    *(float4*)(out + i) = make_float4(a.x + b.x + c.x, a.y + b.y + c.y,
                                      a.z + b.z + c.z, a.w + b.w + c.w);
}

// ---------------- launcher -----------------------------------------------------
extern "C" void kernel_launch(void* const* d_in, const int* in_sizes, int n_in,
                              void* d_out, int out_size)
{
    const float* x     = (const float*)d_in[0];
    const float* cosb  = (const float*)d_in[1];
    const float* sinb  = (const float*)d_in[2];
    const float* ln1w  = (const float*)d_in[3];
    const float* ln1b  = (const float*)d_in[4];
    const float* wqkv  = (const float*)d_in[5];
    const float* bqkv  = (const float*)d_in[6];
    const float* wproj = (const float*)d_in[7];
    const float* bproj = (const float*)d_in[8];
    const float* ln2w  = (const float*)d_in[9];
    const float* ln2b  = (const float*)d_in[10];
    const float* wfc1  = (const float*)d_in[11];
    const float* bfc1  = (const float*)d_in[12];
    const float* wfc2  = (const float*)d_in[13];
    const float* bfc2  = (const float*)d_in[14];
    float* out = (float*)d_out;

    __half *ln1, *ln2, *y, *act, *wqt, *wpt, *w1t, *w2t;
    float *qkv, *h, *mlp;
    cudaGetSymbolAddress((void**)&ln1, g_ln1);
    cudaGetSymbolAddress((void**)&ln2, g_ln2);
    cudaGetSymbolAddress((void**)&qkv, g_qkv);
    cudaGetSymbolAddress((void**)&y,   g_y);
    cudaGetSymbolAddress((void**)&h,   g_h);
    cudaGetSymbolAddress((void**)&mlp, g_mlp);
    cudaGetSymbolAddress((void**)&act, g_act);
    cudaGetSymbolAddress((void**)&wqt, g_wqkv_t);
    cudaGetSymbolAddress((void**)&wpt, g_wproj_t);
    cudaGetSymbolAddress((void**)&w1t, g_wfc1_t);
    cudaGetSymbolAddress((void**)&w2t, g_wfc2_t);

    cudaFuncSetAttribute(hgemm_kernel<0>, cudaFuncAttributeMaxDynamicSharedMemorySize, HSM_BYTES);
    cudaFuncSetAttribute(fused1_kernel, cudaFuncAttributeMaxDynamicSharedMemorySize, F1_SMEM);
    cudaFuncSetAttribute(fused2_kernel, cudaFuncAttributeMaxDynamicSharedMemorySize, HSM_BYTES);

    // 0. fused weight transposes + dual LayerNorm
    prep_kernel<<<TB_ALL + M_TOK, 256>>>(
        wqkv, wqt, wproj, wpt, wfc1, w1t, wfc2, w2t,
        x, ln1w, ln1b, ln2w, ln2b, ln1, ln2);

    // 1. QKV projection -> fp32 qkv
    hgemm_kernel<0><<<dim3(QKV_OUT / 128, M_TOK / 128), 256, HSM_BYTES>>>(
        ln1, wqt, bqkv, qkv, QKV_OUT, C_);

    // 2. RoPE
    rope_kernel<<<M_TOK, 320>>>(qkv, cosb, sinb);

    // 3. fused: flash attention (interleaved) + fc1(+GELU)
    fused1_kernel<<<2560, 256, F1_SMEM>>>(qkv, y, ln2, w1t, bfc1, act);

    // 4. fused: proj + fc2 (interleaved)
    fused2_kernel<<<1024, 256, HSM_BYTES>>>(y, wpt, bproj, h, act, w2t, bfc2, mlp);

    // 5. out = mlp + h + x
    add_kernel<<<(M_TOK * C_) / 1024, 256>>>(mlp, h, x, out);
}